// round 12
// baseline (speedup 1.0000x reference)
#include <cuda_runtime.h>
#include <stdint.h>

#define NCOL     4096
#define TPB      128
#define KSEL     64
#define TGUESS   1.9f      // prefilter guess; exact fallback if it fails
#define BSCALE   512.0f    // bucket scale: bin = min(1023, (int)((fv-TGUESS)*BSCALE))
#define NBIN     1024
#define CAP      768       // candidate capacity (expected ~118 per row)
#define SMALLCAP 64        // boundary-bin brute-force bound
#define NWORD    128       // 4096 elements / 32 bits

// float -> order-preserving uint32 (fallback path only)
__device__ __forceinline__ uint32_t f2k(float f) {
    uint32_t u = __float_as_uint(f);
    return u ^ (uint32_t)((((int32_t)u) >> 31) | (int32_t)0x80000000);
}
__device__ __forceinline__ float k2f(uint32_t k) {
    uint32_t u = (k & 0x80000000u) ? (k ^ 0x80000000u) : ~k;
    return __uint_as_float(u);
}

__device__ __forceinline__ int bucket_of(float fv) {
    int b = (int)((fv - TGUESS) * BSCALE);
    return (b > NBIN - 1) ? (NBIN - 1) : b;     // fv > TGUESS ensures b >= 0
}

__device__ __forceinline__ uint64_t pack_cand(float fv, uint32_t col) {
    // strict total order == "larger value first, then lower column" (top_k tie rule)
    return ((uint64_t)__float_as_uint(fv) << 12) | (uint64_t)(4095u - col);
}

__global__ __launch_bounds__(TPB, 16) void topk_mask_kernel(const float* __restrict__ x,
                                                            float* __restrict__ out) {
    __shared__ uint64_t cand64[CAP];          // 6 KB packed candidates
    __shared__ uint32_t hist[NBIN];           // 4 KB bucket histogram (fallback: first 256)
    __shared__ uint32_t psum[NWORD];          // 8-bin partial sums (512 B)
    __shared__ uint32_t bitmap[NWORD];        // candidate presence ballots (512 B)
    __shared__ uint64_t brute[SMALLCAP];      // boundary-bin gather buffer (512 B)
    __shared__ uint32_t s_pos, s_bin, s_above, s_h, s_cnt2;
    __shared__ uint64_t s_keyT64;
    __shared__ uint32_t keep_bm[NCOL / 32];   // fallback tie path only (512 B)

    const int t    = threadIdx.x;
    const int lane = t & 31;
    const int w    = t >> 5;                  // warp 0..3
    const size_t row_off = (size_t)blockIdx.x * NCOL;
    const float4* __restrict__ xr = (const float4*)(x + row_off);
    float4* __restrict__ outr     = (float4*)(out + row_off);

    if (t == 0) { s_pos = 0; s_cnt2 = 0; s_h = 0xFFFFFFFFu; }
    ((uint4*)hist)[t]       = make_uint4(0, 0, 0, 0);   // zero 1024 bins (2 uint4/thread)
    ((uint4*)hist)[t + TPB] = make_uint4(0, 0, 0, 0);
    __syncthreads();

    // ---- phase 1: 2 batches of 4 float4 loads (MLP=4) + provisional masked store +
    //      presence ballots only (no per-element candidate stores) ----
#pragma unroll
    for (int h = 0; h < 2; h++) {
        float4 qa[4];
#pragma unroll
        for (int g2 = 0; g2 < 4; g2++) qa[g2] = xr[(h * 4 + g2) * TPB + t];
#pragma unroll
        for (int g2 = 0; g2 < 4; g2++) {
            const int g = h * 4 + g2;         // float4 group 0..7
            float4 qv = qa[g2];
            bool p0 = (qv.x > TGUESS), p1 = (qv.y > TGUESS);
            bool p2 = (qv.z > TGUESS), p3 = (qv.w > TGUESS);
            float4 o;
            o.x = p0 ? qv.x : 0.0f;
            o.y = p1 ? qv.y : 0.0f;
            o.z = p2 ? qv.z : 0.0f;
            o.w = p3 ? qv.w : 0.0f;
            outr[g * TPB + t] = o;
            unsigned b0 = __ballot_sync(0xffffffffu, p0);
            unsigned b1 = __ballot_sync(0xffffffffu, p1);
            unsigned b2 = __ballot_sync(0xffffffffu, p2);
            unsigned b3 = __ballot_sync(0xffffffffu, p3);
            if (lane == 0)
                ((uint4*)bitmap)[g * 4 + w] = make_uint4(b0, b1, b2, b3);
        }
    }
    __syncthreads();

    // ---- phase 2a: reconstruct + compact candidates from bitmap (1 word / thread) ----
    // word i = g*16 + w*4 + j; bit l -> col = (g*128 + w*32 + l)*4 + j
    {
        uint32_t m = bitmap[t];
        if (m) {
            const uint32_t gg = (uint32_t)(t >> 4);
            const uint32_t ww = (uint32_t)((t >> 2) & 3);
            const uint32_t jj = (uint32_t)(t & 3);
            uint32_t n = (uint32_t)__popc(m);
            uint32_t base = atomicAdd(&s_pos, n);
            while (m) {
                int l = __ffs(m) - 1;
                m &= m - 1;
                uint32_t col = (gg * 128u + ww * 32u + (uint32_t)l) * 4u + jj;
                float fv = x[row_off + col];          // L2-resident (just read)
                if (base < CAP) cand64[base] = pack_cand(fv, col);
                base++;
                atomicAdd(&hist[bucket_of(fv)], 1u);
            }
        }
    }
    __syncthreads();
    const uint32_t C = s_pos;
    const bool fast = (C >= KSEL && C <= CAP);

    if (fast) {
        // ---- phase 2b: hierarchical conflict-free suffix search for boundary bin ----
        {
            uint4 a = ((const uint4*)hist)[2 * t];         // bins 8t..8t+7
            uint4 b = ((const uint4*)hist)[2 * t + 1];
            psum[t] = a.x + a.y + a.z + a.w + b.x + b.y + b.z + b.w;
        }
        __syncthreads();
        if (t < 32) {
            const int sb = 31 - t;                         // superbin = 4 psums = 32 bins
            uint32_t s32 = psum[4 * sb] + psum[4 * sb + 1] +
                           psum[4 * sb + 2] + psum[4 * sb + 3];
            uint32_t S = s32;
#pragma unroll
            for (int off = 1; off < 32; off <<= 1) {
                uint32_t n = __shfl_up_sync(0xffffffffu, S, off);
                if (t >= off) S += n;
            }
            if (S >= KSEL && (S - s32) < KSEL) {           // boundary superbin: this lane
                uint32_t run = S - s32;
                for (int g = 3; g >= 0; g--) {             // psum entries, descending
                    uint32_t pv = psum[4 * sb + g];
                    if (run + pv >= KSEL) {
                        for (int bb = 8 * (4 * sb + g) + 7;; bb--) {
                            uint32_t hv = hist[bb];
                            if (run + hv >= KSEL) { s_bin = (uint32_t)bb; s_above = run; s_h = hv; break; }
                            run += hv;
                        }
                        break;
                    }
                    run += pv;
                }
            }
        }
        __syncthreads();

        if (s_h <= SMALLCAP) {
            const uint32_t kth2 = KSEL - s_above;          // rank within boundary bin
            const int target = (int)s_bin;
            for (uint32_t i = t; i < C; i += TPB) {
                uint64_t p = cand64[i];
                if (bucket_of(__uint_as_float((uint32_t)(p >> 12))) == target) {
                    uint32_t q = atomicAdd(&s_cnt2, 1u);
                    brute[q] = p;
                }
            }
            __syncthreads();
            if (t < 32) {                                  // all packed values distinct
                uint32_t n = s_cnt2;                       // == s_h
                for (uint32_t i = (uint32_t)t; i < n; i += 32) {
                    uint64_t e = brute[i];
                    uint32_t gt = 0;
                    for (uint32_t j = 0; j < n; j++) gt += (brute[j] > e) ? 1u : 0u;
                    if (gt == kth2 - 1) s_keyT64 = e;      // exact k-th overall
                }
            }
            __syncthreads();
            const uint64_t keyT64 = s_keyT64;

            // ---- phase 3: sparse fix-up — zero candidates strictly below threshold ----
            for (uint32_t i = t; i < C; i += TPB) {
                uint64_t p = cand64[i];
                if (p < keyT64)
                    out[row_off + (4095u - (uint32_t)(p & 0xFFFu))] = 0.0f;
            }
            return;
        }
        __syncthreads();   // degenerate bin: fall through to exact full-row path
    }

    // ================= fallback: exact full-row select + full rewrite =================
    uint32_t prefix = 0, mmask = 0, kth = KSEL, total_eq = 0;
#pragma unroll 1
    for (int pass = 0; pass < 4; pass++) {
        const int shift = 24 - 8 * pass;
        hist[t] = 0; hist[t + TPB] = 0;
        __syncthreads();
        for (int i = t; i < NCOL; i += TPB) {
            uint32_t kk = f2k(x[row_off + i]);
            if ((kk & mmask) == prefix) {
                uint32_t bin = (kk >> shift) & 0xFFu;
                unsigned act = __activemask();
                unsigned grp = __match_any_sync(act, bin);
                if ((grp & ((1u << lane) - 1u)) == 0u)
                    atomicAdd(&hist[bin], (uint32_t)__popc(grp));
            }
        }
        __syncthreads();
        if (t < 32) {       // warp-0 suffix scan over 256 bins, 8 descending bins/lane
            uint32_t run = 0;
#pragma unroll
            for (int j = 0; j < 8; j++) run += hist[255 - t * 8 - j];
            uint32_t excl = run;
#pragma unroll
            for (int off = 1; off < 32; off <<= 1) {
                uint32_t n = __shfl_up_sync(0xffffffffu, excl, off);
                if (t >= off) excl += n;
            }
            excl -= run;
            uint32_t S = excl;
#pragma unroll
            for (int j = 0; j < 8; j++) {
                uint32_t bin = 255u - (uint32_t)(t * 8 + j);
                uint32_t hh = hist[bin];
                S += hh;
                if (S >= kth && (S - hh) < kth) {   // unique boundary bin
                    s_bin = bin; s_above = S - hh; s_h = hh;
                }
            }
        }
        __syncthreads();
        prefix |= (s_bin << shift);
        mmask  |= (0xFFu << shift);
        kth    -= s_above;
        total_eq = s_h;
        __syncthreads();
    }
    const uint32_t need = kth;
    const float Tf = k2f(prefix);
    const bool tie_rank = (total_eq > need);

    if (tie_rank) {
        uint16_t* tiebuf = (uint16_t*)cand64;   // up to 1536 entries; also keep_bm guard
        if (t == 0) s_pos = 0;
        for (int i = t; i < NCOL / 32; i += TPB) keep_bm[i] = 0;
        __syncthreads();
        for (int i = t; i < NCOL; i += TPB) {
            if (x[row_off + i] == Tf) {
                uint32_t p = atomicAdd(&s_pos, 1u);
                if (p < CAP * 4) tiebuf[p] = (uint16_t)i;
            }
        }
        __syncthreads();
        uint32_t total = s_pos;
        if (total <= CAP * 4) {
            for (uint32_t i = t; i < total; i += TPB) {
                uint32_t ci = tiebuf[i], r = 0;
                for (uint32_t j = 0; j < total; j++) r += (tiebuf[j] < ci) ? 1u : 0u;
                if (r < need) atomicOr(&keep_bm[ci >> 5], 1u << (ci & 31));
            }
        } else {
            // degenerate mass-tie row: rank by direct column scan
            for (int i = t; i < NCOL; i += TPB) {
                if (x[row_off + i] == Tf) {
                    uint32_t r = 0;
                    for (int j = 0; j < i; j++) r += (x[row_off + j] == Tf) ? 1u : 0u;
                    if (r < need) atomicOr(&keep_bm[i >> 5], 1u << (i & 31));
                }
            }
        }
        __syncthreads();
#pragma unroll
        for (int g = 0; g < 8; g++) {
            float4 q = xr[g * TPB + t];
            float4 o;
            float* ip = (float*)&q;
            float* op = (float*)&o;
#pragma unroll
            for (int j = 0; j < 4; j++) {
                float fv = ip[j];
                float val = 0.0f;
                if (fv > Tf) val = fv;
                else if (fv == Tf) {
                    uint32_t col = (uint32_t)(g * TPB + t) * 4u + (uint32_t)j;
                    if ((keep_bm[col >> 5] >> (col & 31)) & 1u) val = fv;
                }
                op[j] = val;
            }
            outr[g * TPB + t] = o;
        }
    } else {
#pragma unroll
        for (int g = 0; g < 8; g++) {
            float4 q = xr[g * TPB + t];
            float4 o;
            o.x = (q.x >= Tf) ? q.x : 0.0f;
            o.y = (q.y >= Tf) ? q.y : 0.0f;
            o.z = (q.z >= Tf) ? q.z : 0.0f;
            o.w = (q.w >= Tf) ? q.w : 0.0f;
            outr[g * TPB + t] = o;
        }
    }
}

extern "C" void kernel_launch(void* const* d_in, const int* in_sizes, int n_in,
                              void* d_out, int out_size) {
    const float* x = (const float*)d_in[0];
    float* out = (float*)d_out;
    int rows = in_sizes[0] / NCOL;
    topk_mask_kernel<<<rows, TPB>>>(x, out);
}

// round 13
// speedup vs baseline: 1.1848x; 1.1848x over previous
#include <cuda_runtime.h>
#include <stdint.h>

#define NCOL     4096
#define TPB      256
#define KSEL     64
#define TGUESS   1.9f      // prefilter guess; exact fallback if it fails
#define BSCALE   512.0f    // bucket scale: bin = min(1023, (int)((fv-TGUESS)*BSCALE))
#define NBIN     1024
#define CAP      2048      // candidate capacity (expected ~118 per row)
#define SMALLCAP 64        // boundary-bin brute-force bound
#define NWORD    128       // 4096 elements / 32 bits

// float -> order-preserving uint32 (fallback path only)
__device__ __forceinline__ uint32_t f2k(float f) {
    uint32_t u = __float_as_uint(f);
    return u ^ (uint32_t)((((int32_t)u) >> 31) | (int32_t)0x80000000);
}
__device__ __forceinline__ float k2f(uint32_t k) {
    uint32_t u = (k & 0x80000000u) ? (k ^ 0x80000000u) : ~k;
    return __uint_as_float(u);
}

// inclusive block scan over TPB=256 uint32 values (fallback only). wsum: shared[8].
__device__ __forceinline__ uint32_t block_scan_inc(uint32_t val, uint32_t* wsum, int t) {
    __syncthreads();
    int lane = t & 31, w = t >> 5;
#pragma unroll
    for (int off = 1; off < 32; off <<= 1) {
        uint32_t n = __shfl_up_sync(0xffffffffu, val, off);
        if (lane >= off) val += n;
    }
    if (lane == 31) wsum[w] = val;
    __syncthreads();
    if (w == 0) {
        uint32_t s = (lane < 8) ? wsum[lane] : 0u;
#pragma unroll
        for (int off = 1; off < 8; off <<= 1) {
            uint32_t n = __shfl_up_sync(0xffffffffu, s, off);
            if (lane >= off) s += n;
        }
        if (lane < 8) wsum[lane] = s;
    }
    __syncthreads();
    uint32_t base = (w > 0) ? wsum[w - 1] : 0u;
    return val + base;
}

__device__ __forceinline__ int bucket_of(float fv) {
    int b = (int)((fv - TGUESS) * BSCALE);
    return (b > NBIN - 1) ? (NBIN - 1) : b;     // fv > TGUESS ensures b >= 0
}

__device__ __forceinline__ uint64_t pack_cand(float fv, uint32_t col) {
    // strict total order == "larger value first, then lower column" (top_k tie rule)
    return ((uint64_t)__float_as_uint(fv) << 12) | (uint64_t)(4095u - col);
}

__global__ __launch_bounds__(TPB, 8) void topk_mask_kernel(const float* __restrict__ x,
                                                           float* __restrict__ out) {
    __shared__ uint64_t cand64[CAP];          // 16 KB packed candidates
    __shared__ uint32_t hist[NBIN];           // bucket histogram (fallback uses first 256)
    __shared__ uint32_t bitmap[NWORD];        // candidate presence ballots
    __shared__ uint64_t brute[SMALLCAP];      // boundary-bin gather buffer
    __shared__ uint32_t wsum[8];
    __shared__ uint32_t s_pos, s_bin, s_above, s_h, s_cnt2, s_ok;
    __shared__ uint64_t s_keyT64;
    __shared__ uint32_t keep_bm[NCOL / 32];   // fallback tie path only

    const int t    = threadIdx.x;
    const int lane = t & 31;
    const int w    = t >> 5;
    const size_t row_off = (size_t)blockIdx.x * NCOL;
    const float4* __restrict__ xr = (const float4*)(x + row_off);
    float4* __restrict__ outr     = (float4*)(out + row_off);

    if (t == 0) { s_pos = 0; s_cnt2 = 0; s_ok = 0; }
    ((uint4*)hist)[t] = make_uint4(0, 0, 0, 0);   // zero 1024 bins
    // no barrier: ordering provided by the post-phase-1 barrier (phase 1 never
    // touches hist / s_pos / s_cnt2)

    // ---- phase 1: batched loads (MLP=4) + provisional masked streaming store +
    //      candidate presence recorded as ballot words only ----
    float4 qq[4];
#pragma unroll
    for (int v = 0; v < 4; v++) qq[v] = xr[v * TPB + t];

#pragma unroll
    for (int v = 0; v < 4; v++) {
        float4 qv = qq[v];
        bool p0 = (qv.x > TGUESS), p1 = (qv.y > TGUESS);
        bool p2 = (qv.z > TGUESS), p3 = (qv.w > TGUESS);
        float4 o;
        o.x = p0 ? qv.x : 0.0f;
        o.y = p1 ? qv.y : 0.0f;
        o.z = p2 ? qv.z : 0.0f;
        o.w = p3 ? qv.w : 0.0f;
        __stcs(&outr[v * TPB + t], o);        // streaming: never re-read
        unsigned b0 = __ballot_sync(0xffffffffu, p0);
        unsigned b1 = __ballot_sync(0xffffffffu, p1);
        unsigned b2 = __ballot_sync(0xffffffffu, p2);
        unsigned b3 = __ballot_sync(0xffffffffu, p3);
        if (lane == 0)
            ((uint4*)bitmap)[v * 8 + w] = make_uint4(b0, b1, b2, b3);
    }
    __syncthreads();

    // ---- phase 2a: reconstruct + compact candidates from bitmap (threads 0-127) ----
    // word i: v = i>>5, w = (i>>2)&7, j = i&3; bit l -> col = (v*256 + w*32 + l)*4 + j
    if (t < NWORD) {
        uint32_t m = bitmap[t];
        if (m) {
            const uint32_t vv = (uint32_t)(t >> 5);
            const uint32_t ww = (uint32_t)((t >> 2) & 7);
            const uint32_t jj = (uint32_t)(t & 3);
            uint32_t n = (uint32_t)__popc(m);
            uint32_t base = atomicAdd(&s_pos, n);
            while (m) {
                int l = __ffs(m) - 1;
                m &= m - 1;
                uint32_t col = (vv * 256u + ww * 32u + (uint32_t)l) * 4u + jj;
                float fv = x[row_off + col];          // L2-resident (just read)
                if (base < CAP) cand64[base] = pack_cand(fv, col);
                base++;
                atomicAdd(&hist[bucket_of(fv)], 1u);
            }
        }
    }
    __syncthreads();
    const uint32_t C = s_pos;
    const bool fast = (C >= KSEL && C <= CAP);

    if (fast) {
        // ---- phase 2b: warp 0 does the entire select ----
        if (w == 0) {
            // lane owns 32 descending bins: base = 32*(31-lane)
            const int bbase = 32 * (31 - lane);
            uint4 h4[8];
            uint32_t s32 = 0;
#pragma unroll
            for (int k = 0; k < 8; k++) {
                h4[k] = ((const uint4*)hist)[(bbase >> 2) + k];
                s32 += h4[k].x + h4[k].y + h4[k].z + h4[k].w;
            }
            uint32_t S = s32;
#pragma unroll
            for (int off = 1; off < 32; off <<= 1) {
                uint32_t n = __shfl_up_sync(0xffffffffu, S, off);
                if (lane >= off) S += n;
            }
            if (S >= KSEL && (S - s32) < KSEL) {       // boundary lane: walk own 32 bins
                uint32_t run = S - s32;
                bool done = false;
#pragma unroll
                for (int k = 7; k >= 0; k--) {
                    uint32_t arr[4] = {h4[k].w, h4[k].z, h4[k].y, h4[k].x};
#pragma unroll
                    for (int c = 0; c < 4; c++) {
                        uint32_t hv = arr[c];
                        if (!done) {
                            if (run + hv >= KSEL) {
                                s_bin = (uint32_t)(bbase + 4 * k + 3 - c);
                                s_above = run; s_h = hv;
                                done = true;
                            } else run += hv;
                        }
                    }
                }
            }
            __syncwarp();
            if (s_h <= SMALLCAP) {
                const uint32_t kth2 = KSEL - s_above;  // rank within boundary bin
                const int target = (int)s_bin;
                for (uint32_t i = lane; i < C; i += 32) {
                    uint64_t p = cand64[i];
                    if (bucket_of(__uint_as_float((uint32_t)(p >> 12))) == target) {
                        uint32_t q = atomicAdd(&s_cnt2, 1u);
                        brute[q] = p;
                    }
                }
                __syncwarp();
                uint32_t n = s_cnt2;                   // == s_h
                for (uint32_t i = (uint32_t)lane; i < n; i += 32) {
                    uint64_t e = brute[i];
                    uint32_t gt = 0;
                    for (uint32_t j = 0; j < n; j++) gt += (brute[j] > e) ? 1u : 0u;
                    if (gt == kth2 - 1) { s_keyT64 = e; s_ok = 1; }  // exact k-th
                }
            }
        }
        __syncthreads();

        if (s_ok) {
            const uint64_t keyT64 = s_keyT64;
            // ---- phase 3: sparse fix-up — zero candidates strictly below threshold ----
            for (uint32_t i = t; i < C; i += TPB) {
                uint64_t p = cand64[i];
                if (p < keyT64)
                    out[row_off + (4095u - (uint32_t)(p & 0xFFFu))] = 0.0f;
            }
            return;
        }
        __syncthreads();   // degenerate bin: fall through to exact full-row path
    }

    // ================= fallback: exact full-row select + full rewrite =================
    uint32_t prefix = 0, mmask = 0, kth = KSEL, total_eq = 0;
#pragma unroll 1
    for (int pass = 0; pass < 4; pass++) {
        const int shift = 24 - 8 * pass;
        hist[t] = 0;
        __syncthreads();
        for (int i = t; i < NCOL; i += TPB) {
            uint32_t kk = f2k(x[row_off + i]);
            if ((kk & mmask) == prefix) {
                uint32_t bin = (kk >> shift) & 0xFFu;
                unsigned act = __activemask();
                unsigned grp = __match_any_sync(act, bin);
                if ((grp & ((1u << lane) - 1u)) == 0u)
                    atomicAdd(&hist[bin], (uint32_t)__popc(grp));
            }
        }
        __syncthreads();
        uint32_t hh = hist[255 - t];
        uint32_t S = block_scan_inc(hh, wsum, t);
        if (S >= kth && (S - hh) < kth) {
            s_bin = (uint32_t)(255 - t); s_above = S - hh; s_h = hh;
        }
        __syncthreads();
        prefix |= (s_bin << shift);
        mmask  |= (0xFFu << shift);
        kth    -= s_above;
        total_eq = s_h;
        __syncthreads();
    }
    const uint32_t need = kth;
    const float Tf = k2f(prefix);
    const bool tie_rank = (total_eq > need);

    if (tie_rank) {
        uint16_t* tiebuf = (uint16_t*)cand64;
        if (t == 0) s_pos = 0;
        for (int i = t; i < NCOL / 32; i += TPB) keep_bm[i] = 0;
        __syncthreads();
        for (int i = t; i < NCOL; i += TPB) {
            if (x[row_off + i] == Tf) {
                uint32_t p = atomicAdd(&s_pos, 1u);
                tiebuf[p] = (uint16_t)i;
            }
        }
        __syncthreads();
        uint32_t total = s_pos;
        for (uint32_t i = t; i < total; i += TPB) {
            uint32_t ci = tiebuf[i], r = 0;
            for (uint32_t j = 0; j < total; j++) r += (tiebuf[j] < ci) ? 1u : 0u;
            if (r < need) atomicOr(&keep_bm[ci >> 5], 1u << (ci & 31));
        }
        __syncthreads();
#pragma unroll
        for (int v = 0; v < 4; v++) {
            float4 q = xr[v * TPB + t];
            float4 o;
            float* ip = (float*)&q;
            float* op = (float*)&o;
#pragma unroll
            for (int j = 0; j < 4; j++) {
                float fv = ip[j];
                float val = 0.0f;
                if (fv > Tf) val = fv;
                else if (fv == Tf) {
                    uint32_t col = (uint32_t)(v * TPB + t) * 4u + (uint32_t)j;
                    if ((keep_bm[col >> 5] >> (col & 31)) & 1u) val = fv;
                }
                op[j] = val;
            }
            outr[v * TPB + t] = o;
        }
    } else {
#pragma unroll
        for (int v = 0; v < 4; v++) {
            float4 q = xr[v * TPB + t];
            float4 o;
            o.x = (q.x >= Tf) ? q.x : 0.0f;
            o.y = (q.y >= Tf) ? q.y : 0.0f;
            o.z = (q.z >= Tf) ? q.z : 0.0f;
            o.w = (q.w >= Tf) ? q.w : 0.0f;
            outr[v * TPB + t] = o;
        }
    }
}

extern "C" void kernel_launch(void* const* d_in, const int* in_sizes, int n_in,
                              void* d_out, int out_size) {
    const float* x = (const float*)d_in[0];
    float* out = (float*)d_out;
    int rows = in_sizes[0] / NCOL;
    topk_mask_kernel<<<rows, TPB>>>(x, out);
}

// round 14
// speedup vs baseline: 1.7211x; 1.4527x over previous
#include <cuda_runtime.h>
#include <stdint.h>

#define NCOL     4096
#define TPB      256
#define KSEL     64
#define TGUESS   1.9f      // prefilter guess; exact fallback if it fails
#define BSCALE   512.0f    // bucket scale: bin = min(1023, (int)((fv-TGUESS)*BSCALE))
#define NBIN     1024
#define CAP      2048      // candidate capacity (expected ~118 per row)
#define SMALLCAP 64        // boundary-bin brute-force bound
#define NWORD    128       // 4096 elements / 32 bits

// float -> order-preserving uint32 (fallback path only)
__device__ __forceinline__ uint32_t f2k(float f) {
    uint32_t u = __float_as_uint(f);
    return u ^ (uint32_t)((((int32_t)u) >> 31) | (int32_t)0x80000000);
}
__device__ __forceinline__ float k2f(uint32_t k) {
    uint32_t u = (k & 0x80000000u) ? (k ^ 0x80000000u) : ~k;
    return __uint_as_float(u);
}

// inclusive block scan over TPB=256 uint32 values (fallback only). wsum: shared[8].
__device__ __forceinline__ uint32_t block_scan_inc(uint32_t val, uint32_t* wsum, int t) {
    __syncthreads();
    int lane = t & 31, w = t >> 5;
#pragma unroll
    for (int off = 1; off < 32; off <<= 1) {
        uint32_t n = __shfl_up_sync(0xffffffffu, val, off);
        if (lane >= off) val += n;
    }
    if (lane == 31) wsum[w] = val;
    __syncthreads();
    if (w == 0) {
        uint32_t s = (lane < 8) ? wsum[lane] : 0u;
#pragma unroll
        for (int off = 1; off < 8; off <<= 1) {
            uint32_t n = __shfl_up_sync(0xffffffffu, s, off);
            if (lane >= off) s += n;
        }
        if (lane < 8) wsum[lane] = s;
    }
    __syncthreads();
    uint32_t base = (w > 0) ? wsum[w - 1] : 0u;
    return val + base;
}

__device__ __forceinline__ int bucket_of(float fv) {
    int b = (int)((fv - TGUESS) * BSCALE);
    return (b > NBIN - 1) ? (NBIN - 1) : b;     // fv > TGUESS ensures b >= 0
}

__device__ __forceinline__ uint64_t pack_cand(float fv, uint32_t col) {
    // strict total order == "larger value first, then lower column" (top_k tie rule)
    return ((uint64_t)__float_as_uint(fv) << 12) | (uint64_t)(4095u - col);
}

__global__ __launch_bounds__(TPB, 8) void topk_mask_kernel(const float* __restrict__ x,
                                                           float* __restrict__ out) {
    __shared__ uint64_t cand64[CAP];          // 16 KB packed candidates
    __shared__ uint32_t hist[NBIN];           // bucket histogram (fallback uses first 256)
    __shared__ uint32_t psum[256];            // 4-bin partial sums
    __shared__ uint32_t bitmap[NWORD];        // candidate presence ballots
    __shared__ uint64_t brute[SMALLCAP];      // boundary-bin gather buffer
    __shared__ uint32_t wsum[8];
    __shared__ uint32_t s_pos, s_bin, s_above, s_h, s_cnt2;
    __shared__ uint64_t s_keyT64;
    __shared__ uint32_t keep_bm[NCOL / 32];   // fallback tie path only

    const int t    = threadIdx.x;
    const int lane = t & 31;
    const int w    = t >> 5;
    const size_t row_off = (size_t)blockIdx.x * NCOL;
    const float4* __restrict__ xr = (const float4*)(x + row_off);
    float4* __restrict__ outr     = (float4*)(out + row_off);

    if (t == 0) { s_pos = 0; s_cnt2 = 0; s_h = 0xFFFFFFFFu; }
    ((uint4*)hist)[t] = make_uint4(0, 0, 0, 0);   // zero 1024 bins
    // no barrier needed: ordering provided by the post-phase-1 __syncthreads()
    // (phase 1 never touches hist / s_pos / s_cnt2 / s_h)

    // ---- phase 1: batched loads (MLP=4) + provisional masked store +
    //      candidate presence recorded as ballot words only (no per-element stores) ----
    float4 qq[4];
#pragma unroll
    for (int v = 0; v < 4; v++) qq[v] = xr[v * TPB + t];

#pragma unroll
    for (int v = 0; v < 4; v++) {
        float4 qv = qq[v];
        bool p0 = (qv.x > TGUESS), p1 = (qv.y > TGUESS);
        bool p2 = (qv.z > TGUESS), p3 = (qv.w > TGUESS);
        float4 o;
        o.x = p0 ? qv.x : 0.0f;
        o.y = p1 ? qv.y : 0.0f;
        o.z = p2 ? qv.z : 0.0f;
        o.w = p3 ? qv.w : 0.0f;
        outr[v * TPB + t] = o;
        unsigned b0 = __ballot_sync(0xffffffffu, p0);
        unsigned b1 = __ballot_sync(0xffffffffu, p1);
        unsigned b2 = __ballot_sync(0xffffffffu, p2);
        unsigned b3 = __ballot_sync(0xffffffffu, p3);
        if (lane == 0)
            ((uint4*)bitmap)[v * 8 + w] = make_uint4(b0, b1, b2, b3);
    }
    __syncthreads();

    // ---- phase 2a: reconstruct + compact candidates from bitmap (threads 0-127) ----
    // word i: v = i>>5, w = (i>>2)&7, j = i&3; bit l -> col = (v*256 + w*32 + l)*4 + j
    if (t < NWORD) {
        uint32_t m = bitmap[t];
        if (m) {
            const uint32_t vv = (uint32_t)(t >> 5);
            const uint32_t ww = (uint32_t)((t >> 2) & 7);
            const uint32_t jj = (uint32_t)(t & 3);
            uint32_t n = (uint32_t)__popc(m);
            uint32_t base = atomicAdd(&s_pos, n);
            while (m) {
                int l = __ffs(m) - 1;
                m &= m - 1;
                uint32_t col = (vv * 256u + ww * 32u + (uint32_t)l) * 4u + jj;
                float fv = x[row_off + col];          // L2-resident (just read)
                if (base < CAP) cand64[base] = pack_cand(fv, col);
                base++;
                atomicAdd(&hist[bucket_of(fv)], 1u);
            }
        }
    }
    __syncthreads();
    const uint32_t C = s_pos;
    const bool fast = (C >= KSEL && C <= CAP);

    if (fast) {
        // ---- phase 2b: hierarchical conflict-free suffix search for boundary bin ----
        {
            uint4 h4 = ((const uint4*)hist)[t];            // bins 4t..4t+3
            psum[t] = h4.x + h4.y + h4.z + h4.w;
        }
        __syncthreads();
        if (t < 32) {
            const int sb = 31 - t;                         // lane t owns superbin sb (desc)
            uint4 a = ((const uint4*)psum)[2 * sb];
            uint4 b = ((const uint4*)psum)[2 * sb + 1];
            uint32_t s8 = a.x + a.y + a.z + a.w + b.x + b.y + b.z + b.w;
            uint32_t S = s8;
#pragma unroll
            for (int off = 1; off < 32; off <<= 1) {
                uint32_t n = __shfl_up_sync(0xffffffffu, S, off);
                if (t >= off) S += n;
            }
            if (S >= KSEL && (S - s8) < KSEL) {            // boundary superbin: this lane
                uint32_t run = S - s8;
                for (int g = 7; g >= 0; g--) {
                    uint32_t pv = psum[8 * sb + g];
                    if (run + pv >= KSEL) {
                        for (int bb = 4 * (8 * sb + g) + 3;; bb--) {
                            uint32_t hv = hist[bb];
                            if (run + hv >= KSEL) { s_bin = (uint32_t)bb; s_above = run; s_h = hv; break; }
                            run += hv;
                        }
                        break;
                    }
                    run += pv;
                }
            }
        }
        __syncthreads();

        if (s_h <= SMALLCAP) {
            const uint32_t kth2 = KSEL - s_above;          // rank within boundary bin
            const int target = (int)s_bin;
            for (uint32_t i = t; i < C; i += TPB) {
                uint64_t p = cand64[i];
                if (bucket_of(__uint_as_float((uint32_t)(p >> 12))) == target) {
                    uint32_t q = atomicAdd(&s_cnt2, 1u);
                    brute[q] = p;
                }
            }
            __syncthreads();
            if (t < 32) {                                  // all packed values distinct
                uint32_t n = s_cnt2;                       // == s_h
                for (uint32_t i = (uint32_t)t; i < n; i += 32) {
                    uint64_t e = brute[i];
                    uint32_t gt = 0;
                    for (uint32_t j = 0; j < n; j++) gt += (brute[j] > e) ? 1u : 0u;
                    if (gt == kth2 - 1) s_keyT64 = e;      // exact k-th overall
                }
            }
            __syncthreads();
            const uint64_t keyT64 = s_keyT64;

            // ---- phase 3: sparse fix-up — zero candidates strictly below threshold ----
            for (uint32_t i = t; i < C; i += TPB) {
                uint64_t p = cand64[i];
                if (p < keyT64)
                    out[row_off + (4095u - (uint32_t)(p & 0xFFFu))] = 0.0f;
            }
            return;
        }
        __syncthreads();   // degenerate bin: fall through to exact full-row path
    }

    // ================= fallback: exact full-row select + full rewrite =================
    uint32_t prefix = 0, mmask = 0, kth = KSEL, total_eq = 0;
#pragma unroll 1
    for (int pass = 0; pass < 4; pass++) {
        const int shift = 24 - 8 * pass;
        hist[t] = 0;
        __syncthreads();
        for (int i = t; i < NCOL; i += TPB) {
            uint32_t kk = f2k(x[row_off + i]);
            if ((kk & mmask) == prefix) {
                uint32_t bin = (kk >> shift) & 0xFFu;
                unsigned act = __activemask();
                unsigned grp = __match_any_sync(act, bin);
                if ((grp & ((1u << lane) - 1u)) == 0u)
                    atomicAdd(&hist[bin], (uint32_t)__popc(grp));
            }
        }
        __syncthreads();
        uint32_t hh = hist[255 - t];
        uint32_t S = block_scan_inc(hh, wsum, t);
        if (S >= kth && (S - hh) < kth) {
            s_bin = (uint32_t)(255 - t); s_above = S - hh; s_h = hh;
        }
        __syncthreads();
        prefix |= (s_bin << shift);
        mmask  |= (0xFFu << shift);
        kth    -= s_above;
        total_eq = s_h;
        __syncthreads();
    }
    const uint32_t need = kth;
    const float Tf = k2f(prefix);
    const bool tie_rank = (total_eq > need);

    if (tie_rank) {
        uint16_t* tiebuf = (uint16_t*)cand64;
        if (t == 0) s_pos = 0;
        for (int i = t; i < NCOL / 32; i += TPB) keep_bm[i] = 0;
        __syncthreads();
        for (int i = t; i < NCOL; i += TPB) {
            if (x[row_off + i] == Tf) {
                uint32_t p = atomicAdd(&s_pos, 1u);
                tiebuf[p] = (uint16_t)i;
            }
        }
        __syncthreads();
        uint32_t total = s_pos;
        for (uint32_t i = t; i < total; i += TPB) {
            uint32_t ci = tiebuf[i], r = 0;
            for (uint32_t j = 0; j < total; j++) r += (tiebuf[j] < ci) ? 1u : 0u;
            if (r < need) atomicOr(&keep_bm[ci >> 5], 1u << (ci & 31));
        }
        __syncthreads();
#pragma unroll
        for (int v = 0; v < 4; v++) {
            float4 q = xr[v * TPB + t];
            float4 o;
            float* ip = (float*)&q;
            float* op = (float*)&o;
#pragma unroll
            for (int j = 0; j < 4; j++) {
                float fv = ip[j];
                float val = 0.0f;
                if (fv > Tf) val = fv;
                else if (fv == Tf) {
                    uint32_t col = (uint32_t)(v * TPB + t) * 4u + (uint32_t)j;
                    if ((keep_bm[col >> 5] >> (col & 31)) & 1u) val = fv;
                }
                op[j] = val;
            }
            outr[v * TPB + t] = o;
        }
    } else {
#pragma unroll
        for (int v = 0; v < 4; v++) {
            float4 q = xr[v * TPB + t];
            float4 o;
            o.x = (q.x >= Tf) ? q.x : 0.0f;
            o.y = (q.y >= Tf) ? q.y : 0.0f;
            o.z = (q.z >= Tf) ? q.z : 0.0f;
            o.w = (q.w >= Tf) ? q.w : 0.0f;
            outr[v * TPB + t] = o;
        }
    }
}

extern "C" void kernel_launch(void* const* d_in, const int* in_sizes, int n_in,
                              void* d_out, int out_size) {
    const float* x = (const float*)d_in[0];
    float* out = (float*)d_out;
    int rows = in_sizes[0] / NCOL;
    topk_mask_kernel<<<rows, TPB>>>(x, out);
}